// round 10
// baseline (speedup 1.0000x reference)
#include <cuda_runtime.h>
#include <cuda_bf16.h>

#define N_NODES 50000
#define N_EDGES 800000
#define D_IN    128
#define D_OUT   64

// Scratch for h = x @ W (12.8 MB fp32; L2-resident during scatter)
__device__ float g_h[N_NODES * D_OUT];

// Packed fp32x2 FMA (Blackwell): d = a*b + d per 32-bit lane of the 64-bit regs.
__device__ __forceinline__ void ffma2(unsigned long long& d,
                                      unsigned long long a,
                                      unsigned long long b) {
    asm("fma.rn.f32x2 %0, %1, %2, %0;" : "+l"(d) : "l"(a), "l"(b));
}

// ---------------------------------------------------------------------------
// Kernel 1: h = x @ W   (50000x128 @ 128x64)
// 256 threads/block, tile = 128 rows x 64 cols (full D_OUT).
// Thread (rg, cg): 4 rows x 8 cols, accumulated as 16 f32x2 pairs (FFMA2).
// K processed in 8 chunks of 16: Xs[128][20] = 10 KB staged per chunk.
// Static smem total = 32 KB (Ws) + 10 KB (Xs) = 42 KB -> 3-5 CTAs/SM.
// Xs stride 20 floats = 80 B: 16B-aligned (float4 ok), 4-row offset = 80
// floats = 16 mod 32 banks -> only 2-way conflict on x scalar reads.
// ---------------------------------------------------------------------------
#define KC 16   // k-chunk

__global__ __launch_bounds__(256) void gemm_kernel(
    const float* __restrict__ x,
    const float* __restrict__ w,
    float* __restrict__ h)
{
    __shared__ __align__(16) float Ws[D_IN][D_OUT];  // 32 KB
    __shared__ __align__(16) float Xs[128][20];      // 10 KB

    const int t = threadIdx.x;
    const int row0 = blockIdx.x * 128;
    const int rg = t >> 3;    // 0..31 -> rows rg*4 .. rg*4+3
    const int cg = t & 7;     // 0..7  -> cols cg*8 .. cg*8+7

    // Stage W once: 2048 float4, 8 per thread
    {
        const float4* w4 = (const float4*)w;
        #pragma unroll
        for (int i = 0; i < 8; i++) {
            const int idx = t + i * 256;        // float4 index into [128][16]
            const int kk = idx >> 4, cc = (idx & 15) * 4;
            *(float4*)&Ws[kk][cc] = w4[idx];
        }
    }

    unsigned long long acc[4][4] = {};  // [row][col-pair2] each = 2 fp32

    #pragma unroll 1
    for (int pass = 0; pass < D_IN / KC; pass++) {
        __syncthreads();
        // Stage Xs chunk: 128 rows x 16 k = 512 float4, 2 per thread
        #pragma unroll
        for (int i = 0; i < 2; i++) {
            const int idx = t + i * 256;        // float4 idx into [128][4]
            const int rr = idx >> 2, c4 = idx & 3;
            int grow = row0 + rr;
            if (grow > N_NODES - 1) grow = N_NODES - 1;
            *(float4*)&Xs[rr][c4 * 4] =
                *(const float4*)&x[(size_t)grow * D_IN + pass * KC + c4 * 4];
        }
        __syncthreads();

        #pragma unroll 4
        for (int k = 0; k < KC; k++) {
            const ulonglong2 wv0 = *(const ulonglong2*)&Ws[pass * KC + k][cg * 8];
            const ulonglong2 wv1 = *(const ulonglong2*)&Ws[pass * KC + k][cg * 8 + 4];
            #pragma unroll
            for (int i = 0; i < 4; i++) {
                const float xv = Xs[rg * 4 + i][k];
                unsigned long long xp;
                asm("mov.b64 %0, {%1, %1};" : "=l"(xp) : "r"(__float_as_uint(xv)));
                ffma2(acc[i][0], xp, wv0.x);
                ffma2(acc[i][1], xp, wv0.y);
                ffma2(acc[i][2], xp, wv1.x);
                ffma2(acc[i][3], xp, wv1.y);
            }
        }
    }

    // Store: 4 rows x 2 x 16B per thread
    #pragma unroll
    for (int i = 0; i < 4; i++) {
        const int grow = row0 + rg * 4 + i;
        if (grow < N_NODES) {
            float* hp = h + (size_t)grow * D_OUT + cg * 8;
            ulonglong2 v0; v0.x = acc[i][0]; v0.y = acc[i][1];
            ulonglong2 v1; v1.x = acc[i][2]; v1.y = acc[i][3];
            *(ulonglong2*)(hp)     = v0;
            *(ulonglong2*)(hp + 4) = v1;
        }
    }
}

// ---------------------------------------------------------------------------
// Kernel 2: out[i][c] = bias[c]  (float4 broadcast; d_out is poisoned)
// ---------------------------------------------------------------------------
__global__ __launch_bounds__(256) void init_kernel(
    float* __restrict__ out,
    const float* __restrict__ bias)
{
    __shared__ float4 bs4[16];
    if (threadIdx.x < 16) bs4[threadIdx.x] = ((const float4*)bias)[threadIdx.x];
    __syncthreads();
    const int i = blockIdx.x * blockDim.x + threadIdx.x;   // float4 index
    if (i < N_NODES * D_OUT / 4) ((float4*)out)[i] = bs4[i & 15];
}

// ---------------------------------------------------------------------------
// Kernel 3: scatter-add (unchanged from the passing 61us kernel).
// 128 threads = 8 subgroups of 16 lanes; lane owns a float4 of dims.
// Sorted dst -> run-length accumulate in regs, atomics at run boundaries.
// ---------------------------------------------------------------------------
#define EPB 512

__device__ __forceinline__ void flush_acc(float* out, int node, int lane, float4 a)
{
    float* p = &out[(size_t)node * D_OUT + lane * 4];
    atomicAdd(p + 0, a.x);
    atomicAdd(p + 1, a.y);
    atomicAdd(p + 2, a.z);
    atomicAdd(p + 3, a.w);
}

__global__ __launch_bounds__(128) void scatter_kernel(
    const int*   __restrict__ src,
    const int*   __restrict__ dst,
    const float* __restrict__ vals,
    const float* __restrict__ h,
    float*       __restrict__ out)
{
    __shared__ __align__(16) int   s_src[EPB];
    __shared__ __align__(16) int   s_dst[EPB];
    __shared__ __align__(16) float s_val[EPB];

    const int t = threadIdx.x;
    const int e0 = blockIdx.x * EPB;
    int n = N_EDGES - e0;
    if (n > EPB) n = EPB;

    {
        const int i = t;
        const int e = e0 + i * 4;
        if (e + 3 < N_EDGES) {
            *(int4*)  &s_src[i * 4] = *(const int4*)  &src[e];
            *(int4*)  &s_dst[i * 4] = *(const int4*)  &dst[e];
            *(float4*)&s_val[i * 4] = *(const float4*)&vals[e];
        } else {
            #pragma unroll
            for (int j = 0; j < 4; j++) {
                if (e + j < N_EDGES) {
                    s_src[i * 4 + j] = src[e + j];
                    s_dst[i * 4 + j] = dst[e + j];
                    s_val[i * 4 + j] = vals[e + j];
                }
            }
        }
    }
    __syncthreads();

    const int sg   = t >> 4;
    const int lane = t & 15;
    const int lo = sg * (EPB / 8);
    int hi = lo + (EPB / 8);
    if (hi > n) hi = n;
    if (lo >= hi) return;

    int    d0 = s_dst[lo];
    float  v0 = s_val[lo];
    float4 h0 = *(const float4*)&h[(size_t)s_src[lo] * D_OUT + lane * 4];

    int cur = d0;
    float4 acc = make_float4(0.f, 0.f, 0.f, 0.f);

    for (int i = lo; i < hi - 1; i++) {
        const int    d1 = s_dst[i + 1];
        const float  v1 = s_val[i + 1];
        const float4 h1 = *(const float4*)&h[(size_t)s_src[i + 1] * D_OUT + lane * 4];

        if (d0 != cur) {
            flush_acc(out, cur, lane, acc);
            acc = make_float4(0.f, 0.f, 0.f, 0.f);
            cur = d0;
        }
        acc.x = fmaf(v0, h0.x, acc.x);
        acc.y = fmaf(v0, h0.y, acc.y);
        acc.z = fmaf(v0, h0.z, acc.z);
        acc.w = fmaf(v0, h0.w, acc.w);

        d0 = d1; v0 = v1; h0 = h1;
    }
    if (d0 != cur) {
        flush_acc(out, cur, lane, acc);
        acc = make_float4(0.f, 0.f, 0.f, 0.f);
        cur = d0;
    }
    acc.x = fmaf(v0, h0.x, acc.x);
    acc.y = fmaf(v0, h0.y, acc.y);
    acc.z = fmaf(v0, h0.z, acc.z);
    acc.w = fmaf(v0, h0.w, acc.w);
    flush_acc(out, cur, lane, acc);
}

// ---------------------------------------------------------------------------
// Launch.  Inputs: x, edge_src, edge_dst, edge_vals, weight, bias
// ---------------------------------------------------------------------------
extern "C" void kernel_launch(void* const* d_in, const int* in_sizes, int n_in,
                              void* d_out, int out_size)
{
    const float* x        = (const float*)d_in[0];
    const int*   edge_src = (const int*)  d_in[1];
    const int*   edge_dst = (const int*)  d_in[2];
    const float* edge_val = (const float*)d_in[3];
    const float* weight   = (const float*)d_in[4];
    const float* bias     = (const float*)d_in[5];
    float*       out      = (float*)d_out;

    float* h;
    cudaGetSymbolAddress((void**)&h, g_h);

    gemm_kernel<<<(N_NODES + 127) / 128, 256>>>(x, weight, h);

    init_kernel<<<(N_NODES * D_OUT / 4 + 255) / 256, 256>>>(out, bias);

    scatter_kernel<<<(N_EDGES + EPB - 1) / EPB, 128>>>(
        edge_src, edge_dst, edge_val, h, out);
}